// round 4
// baseline (speedup 1.0000x reference)
#include <cuda_runtime.h>

// CompressKV: y[b,m,h,d] = (sum_k x[b, m*16+k, h, d]*w[k] + sum_k pe[k,d]*w[k]) / 32
// x (4,16384,8,128) f32, w (32) f32, pe (32,128) f32, y (4,1023,8,128) f32.
//
// R4: DRAM-page-local mapping. One 256-thread CTA consumes whole 4 KB token
// rows (all 8 heads x 128 dims) and rolls over 8 consecutive output windows.
// Each 16-row group is loaded once per thread and feeds two windows in
// registers (k=16..31 of the older, k=0..15 of the newer).

#define CB 4
#define CN 16384
#define CH 8
#define CD 128
#define CK 32
#define CSTRIDE 16
#define CM 1023            // (16384 - 32)/16 + 1
#define MCHUNK 8
#define NCHUNK 128         // ceil(CM / MCHUNK)
#define LANES 256          // float4 lanes per token row (CH*CD/4)

__global__ __launch_bounds__(256, 3)
void compresskv_kernel(const float4* __restrict__ x,
                       const float*  __restrict__ w,
                       const float4* __restrict__ pe,
                       float4*       __restrict__ y)
{
    __shared__ float4 sbias[CD / 4];

    const int c  = threadIdx.x;          // lane: h = c>>5, d4 = c&31
    const int d4 = c & 31;

    // weights -> registers (each thread keeps all 32; broadcast loads)
    float wk[CK];
#pragma unroll
    for (int k = 0; k < CK; ++k) wk[k] = __ldg(&w[k]);

    // one warp computes bias[d4] = sum_k pe[k][d]*w[k] for the block
    if (c < CD / 4) {
        float bx = 0.f, by = 0.f, bz = 0.f, bw = 0.f;
#pragma unroll
        for (int k = 0; k < CK; ++k) {
            float4 p = __ldg(&pe[k * (CD / 4) + c]);
            bx = fmaf(wk[k], p.x, bx);
            by = fmaf(wk[k], p.y, by);
            bz = fmaf(wk[k], p.z, bz);
            bw = fmaf(wk[k], p.w, bw);
        }
        float4 o; o.x = bx; o.y = by; o.z = bz; o.w = bw;
        sbias[c] = o;
    }
    __syncthreads();
    const float4 bias = sbias[d4];

    const int m0 = blockIdx.x * MCHUNK;
    const int b  = blockIdx.y;

    const float4* xb = x + (size_t)b * CN * LANES + c;   // my lane of token rows
    float4*       yb = y + (size_t)b * CM * LANES + c;

    // accA: older window (receives k=16..31 this group); accB: newer (k=0..15)
    float aAx = 0.f, aAy = 0.f, aAz = 0.f, aAw = 0.f;
    float aBx = 0.f, aBy = 0.f, aBz = 0.f, aBw = 0.f;

#pragma unroll
    for (int g = 0; g <= MCHUNK; ++g) {
        const int mg = m0 + g;           // group index == newer window index
        if (mg <= 1023) {                // rows 16*mg .. 16*mg+15 exist
            const float4* xp = xb + (size_t)(mg * CSTRIDE) * LANES;
#pragma unroll
            for (int r = 0; r < CSTRIDE; ++r) {
                float4 v = __ldg(&xp[(size_t)r * LANES]);
                if (g > 0) {
                    aAx = fmaf(wk[CSTRIDE + r], v.x, aAx);
                    aAy = fmaf(wk[CSTRIDE + r], v.y, aAy);
                    aAz = fmaf(wk[CSTRIDE + r], v.z, aAz);
                    aAw = fmaf(wk[CSTRIDE + r], v.w, aAw);
                }
                if (g < MCHUNK) {
                    aBx = fmaf(wk[r], v.x, aBx);
                    aBy = fmaf(wk[r], v.y, aBy);
                    aBz = fmaf(wk[r], v.z, aBz);
                    aBw = fmaf(wk[r], v.w, aBw);
                }
            }
        }
        if (g > 0) {
            const int m = mg - 1;        // window m complete
            if (m < CM) {
                float4 o;
                o.x = (aAx + bias.x) * 0.03125f;
                o.y = (aAy + bias.y) * 0.03125f;
                o.z = (aAz + bias.z) * 0.03125f;
                o.w = (aAw + bias.w) * 0.03125f;
                yb[(size_t)m * LANES] = o;
            }
        }
        aAx = aBx; aAy = aBy; aAz = aBz; aAw = aBw;
        aBx = 0.f; aBy = 0.f; aBz = 0.f; aBw = 0.f;
    }
}

extern "C" void kernel_launch(void* const* d_in, const int* in_sizes, int n_in,
                              void* d_out, int out_size)
{
    const float4* x  = (const float4*)d_in[0];
    const float*  w  = (const float*) d_in[1];
    const float4* pe = (const float4*)d_in[2];
    float4*       y  = (float4*)d_out;

    dim3 grid(NCHUNK, CB);               // (128, 4) = 512 CTAs, each streams 576 KB
    dim3 block(256);
    compresskv_kernel<<<grid, block>>>(x, w, pe, y);
}

// round 5
// speedup vs baseline: 1.2534x; 1.2534x over previous
#include <cuda_runtime.h>

// CompressKV: y[b,m,h,d] = (sum_k x[b, m*16+k, h, d]*w[k] + sum_k pe[k,d]*w[k]) / 32
// x (4,16384,8,128) f32, w (32) f32, pe (32,128) f32, y (4,1023,8,128) f32.
//
// R5 = R3 (best: 49.6us) with ONE change: grid axes transposed so h is the
// fastest block index. Co-resident CTAs then cover all 8 heads of the same
// token range -> every hot 4 KB x row is demanded wall-to-wall concurrently
// (dense DRAM row bursts) instead of in 512 B slices spread over the launch.

#define CB 4
#define CN 16384
#define CH 8
#define CD 128
#define CK 32
#define CSTRIDE 16
#define CM 1023          // (16384 - 32)/16 + 1
#define MCHUNK 8
#define ROW4 (CH * (CD / 4))   // 256 float4 between consecutive n

__global__ __launch_bounds__(256, 4)
void compresskv_kernel(const float4* __restrict__ x,
                       const float*  __restrict__ w,
                       const float4* __restrict__ pe,
                       float4*       __restrict__ y)
{
    __shared__ float  sw[CK];
    __shared__ float4 sbias[CD / 4];

    const int tid = threadIdx.x;
    const int d4  = tid & 31;            // float4 lane within 128-float row
    const int j   = tid >> 5;            // local m within chunk

    if (tid < CK) sw[tid] = w[tid];
    __syncthreads();

    // one warp computes bias[d] = sum_k pe[k][d]*w[k] for the whole block
    if (tid < CD / 4) {
        float bx = 0.f, by = 0.f, bz = 0.f, bw = 0.f;
#pragma unroll
        for (int k = 0; k < CK; ++k) {
            float4 p  = __ldg(&pe[k * (CD / 4) + tid]);
            float  wv = sw[k];
            bx = fmaf(wv, p.x, bx);
            by = fmaf(wv, p.y, by);
            bz = fmaf(wv, p.z, bz);
            bw = fmaf(wv, p.w, bw);
        }
        float4 o; o.x = bx; o.y = by; o.z = bz; o.w = bw;
        sbias[tid] = o;
    }
    __syncthreads();

    const int h = blockIdx.x;                    // FASTEST axis: all 8 heads co-resident
    const int m = blockIdx.y * MCHUNK + j;
    const int b = blockIdx.z;

    if (m < CM) {
        const float4* xp = x + ((size_t)((b * CN + m * CSTRIDE) * CH + h)) * (CD / 4) + d4;

        float ax = 0.f, ay = 0.f, az = 0.f, aw = 0.f;
#pragma unroll
        for (int k = 0; k < CK; ++k) {
            float4 v  = __ldg(&xp[(size_t)k * ROW4]);
            float  wv = sw[k];
            ax = fmaf(wv, v.x, ax);
            ay = fmaf(wv, v.y, ay);
            az = fmaf(wv, v.z, az);
            aw = fmaf(wv, v.w, aw);
        }

        float4 bias = sbias[d4];
        float4 out;
        out.x = (ax + bias.x) * 0.03125f;
        out.y = (ay + bias.y) * 0.03125f;
        out.z = (az + bias.z) * 0.03125f;
        out.w = (aw + bias.w) * 0.03125f;
        y[((size_t)((b * CM + m) * CH + h)) * (CD / 4) + d4] = out;
    }
}

extern "C" void kernel_launch(void* const* d_in, const int* in_sizes, int n_in,
                              void* d_out, int out_size)
{
    const float4* x  = (const float4*)d_in[0];
    const float*  w  = (const float*) d_in[1];
    const float4* pe = (const float4*)d_in[2];
    float4*       y  = (float4*)d_out;

    dim3 grid(CH, (CM + MCHUNK - 1) / MCHUNK, CB);   // (8, 128, 4) — h fastest
    dim3 block(256);
    compresskv_kernel<<<grid, block>>>(x, w, pe, y);
}

// round 6
// speedup vs baseline: 1.2986x; 1.0361x over previous
#include <cuda_runtime.h>
#include <cstdint>

// CompressKV: y[b,m,h,d] = (sum_k x[b, m*16+k, h, d]*w[k] + sum_k pe[k,d]*w[k]) / 32
// x (4,16384,8,128) f32, w (32) f32, pe (32,128) f32, y (4,1023,8,128) f32.
//
// R6: TMA bulk-copy streamer. x is contiguous over (h,d): 4 KB per token.
// Each CTA handles 4 consecutive windows; streams 10 groups of 8 tokens
// (32 KB contiguous) through a 3-stage smem ring via cp.async.bulk +
// mbarrier. Rolling A/B register accumulators: each token read once from
// smem, feeds two overlapping windows.

#define CB 4
#define CN 16384
#define CH 8
#define CD 128
#define CK 32
#define CM 1023
#define WCHUNK 4                    // windows per CTA
#define NCHUNKS 256                 // ceil(1023/4)
#define GTOK 8                      // tokens per group
#define GROUP_BYTES (GTOK * CH * CD * 4)   // 32768
#define NGROUPS 10                  // groups per CTA (4*2 + 2 overlap)
#define STAGES 3
#define LANES 256                   // float4 lanes per token row
#define SMEM_DATA_OFF 1024
#define SMEM_TOTAL (SMEM_DATA_OFF + STAGES * GROUP_BYTES)   // 99328
#define MAX_T 2047                  // last valid 8-token group index

__device__ __forceinline__ uint32_t smem_u32(const void* p) {
    uint32_t a;
    asm("{ .reg .u64 t; cvta.to.shared.u64 t, %1; cvt.u32.u64 %0, t; }"
        : "=r"(a) : "l"(p));
    return a;
}

__device__ __forceinline__ void mbar_init(uint32_t mb, uint32_t cnt) {
    asm volatile("mbarrier.init.shared.b64 [%0], %1;" :: "r"(mb), "r"(cnt) : "memory");
}
__device__ __forceinline__ void mbar_expect_tx(uint32_t mb, uint32_t bytes) {
    asm volatile("mbarrier.arrive.expect_tx.shared.b64 _, [%0], %1;"
                 :: "r"(mb), "r"(bytes) : "memory");
}
__device__ __forceinline__ void mbar_wait(uint32_t mb, uint32_t parity) {
    asm volatile(
        "{\n\t"
        ".reg .pred P;\n\t"
        "WL_%=:\n\t"
        "mbarrier.try_wait.parity.acquire.cta.shared::cta.b64 P, [%0], %1, 0x989680;\n\t"
        "@P bra.uni WD_%=;\n\t"
        "bra.uni WL_%=;\n\t"
        "WD_%=:\n\t"
        "}"
        :: "r"(mb), "r"(parity) : "memory");
}
__device__ __forceinline__ void bulk_ld(uint32_t dst, const void* src, uint32_t mb) {
    asm volatile("cp.async.bulk.shared::cta.global.mbarrier::complete_tx::bytes "
                 "[%0], [%1], %2, [%3];"
                 :: "r"(dst), "l"(src), "n"(GROUP_BYTES), "r"(mb) : "memory");
}

__global__ __launch_bounds__(256, 2)
void compresskv_kernel(const float* __restrict__ x,
                       const float* __restrict__ w,
                       const float4* __restrict__ pe,
                       float4*      __restrict__ y)
{
    extern __shared__ char smem[];
    const uint32_t sbase = smem_u32(smem);
    const int tid = threadIdx.x;
    const int m0  = blockIdx.x * WCHUNK;
    const int b   = blockIdx.y;
    const int t0  = 2 * m0;                  // first global 8-token group

    if (tid == 0) {
#pragma unroll
        for (int s = 0; s < STAGES; ++s) mbar_init(sbase + 8u * s, 1);
    }
    __syncthreads();

    const char* xb = (const char*)x + (size_t)b * CN * (CH * CD * 4);

    // prologue: fill the ring
    if (tid == 0) {
#pragma unroll
        for (int j = 0; j < STAGES; ++j) {
            if (t0 + j <= MAX_T) {
                mbar_expect_tx(sbase + 8u * j, GROUP_BYTES);
                bulk_ld(sbase + SMEM_DATA_OFF + (uint32_t)j * GROUP_BYTES,
                        xb + (size_t)(t0 + j) * GROUP_BYTES, sbase + 8u * j);
            }
        }
    }

    // weights + bias (registers; pe is 16 KB, L2 resident)
    float wk[CK];
#pragma unroll
    for (int k = 0; k < CK; ++k) wk[k] = __ldg(&w[k]);

    float4 bias; bias.x = bias.y = bias.z = bias.w = 0.f;
#pragma unroll
    for (int k = 0; k < CK; ++k) {
        float4 p = __ldg(&pe[k * (CD / 4) + (tid & 31)]);
        bias.x = fmaf(wk[k], p.x, bias.x);
        bias.y = fmaf(wk[k], p.y, bias.y);
        bias.z = fmaf(wk[k], p.z, bias.z);
        bias.w = fmaf(wk[k], p.w, bias.w);
    }

    float4* yb = y + (size_t)b * CM * LANES + tid;

    float aAx = 0.f, aAy = 0.f, aAz = 0.f, aAw = 0.f;   // older window
    float aBx = 0.f, aBy = 0.f, aBz = 0.f, aBw = 0.f;   // newer window

#pragma unroll
    for (int j = 0; j < NGROUPS; ++j) {
        if (t0 + j <= MAX_T) {                           // uniform per block
            const int st = j % STAGES;
            mbar_wait(sbase + 8u * st, (j / STAGES) & 1);

            const float4* sp =
                (const float4*)(smem + SMEM_DATA_OFF + (size_t)st * GROUP_BYTES) + tid;
            const int koffB = 8 * (j & 1);               // compile-time
            const int koffA = 16 + 8 * (j & 1);
#pragma unroll
            for (int r = 0; r < GTOK; ++r) {
                float4 v = sp[r * LANES];
                if (j >= 2) {                            // older window is ours
                    aAx = fmaf(wk[koffA + r], v.x, aAx);
                    aAy = fmaf(wk[koffA + r], v.y, aAy);
                    aAz = fmaf(wk[koffA + r], v.z, aAz);
                    aAw = fmaf(wk[koffA + r], v.w, aAw);
                }
                if (j <= 7) {                            // newer window is ours
                    aBx = fmaf(wk[koffB + r], v.x, aBx);
                    aBy = fmaf(wk[koffB + r], v.y, aBy);
                    aBz = fmaf(wk[koffB + r], v.z, aBz);
                    aBw = fmaf(wk[koffB + r], v.w, aBw);
                }
            }
            __syncthreads();                             // stage st free
            if (tid == 0 && j + STAGES < NGROUPS && t0 + j + STAGES <= MAX_T) {
                mbar_expect_tx(sbase + 8u * st, GROUP_BYTES);
                bulk_ld(sbase + SMEM_DATA_OFF + (uint32_t)st * GROUP_BYTES,
                        xb + (size_t)(t0 + j + STAGES) * GROUP_BYTES, sbase + 8u * st);
            }

            if (j & 1) {                                 // window transition
                if (j >= 3) {
                    const int wdx = m0 + (j - 3) / 2;    // complete window
                    if (wdx <= CM - 1) {
                        float4 o;
                        o.x = (aAx + bias.x) * 0.03125f;
                        o.y = (aAy + bias.y) * 0.03125f;
                        o.z = (aAz + bias.z) * 0.03125f;
                        o.w = (aAw + bias.w) * 0.03125f;
                        yb[(size_t)wdx * LANES] = o;
                    }
                }
                aAx = aBx; aAy = aBy; aAz = aBz; aAw = aBw;
                aBx = 0.f; aBy = 0.f; aBz = 0.f; aBw = 0.f;
            }
        }
    }
}

extern "C" void kernel_launch(void* const* d_in, const int* in_sizes, int n_in,
                              void* d_out, int out_size)
{
    const float*  x  = (const float*) d_in[0];
    const float*  w  = (const float*) d_in[1];
    const float4* pe = (const float4*)d_in[2];
    float4*       y  = (float4*)d_out;

    static bool attr_set = false;
    if (!attr_set) {
        cudaFuncSetAttribute(compresskv_kernel,
                             cudaFuncAttributeMaxDynamicSharedMemorySize, SMEM_TOTAL);
        attr_set = true;
    }

    dim3 grid(NCHUNKS, CB);                  // (256, 4) = 1024 CTAs
    dim3 block(256);
    compresskv_kernel<<<grid, block, SMEM_TOTAL>>>(x, w, pe, y);
}

// round 7
// speedup vs baseline: 1.3003x; 1.0013x over previous
#include <cuda_runtime.h>
#include <cstdint>

// CompressKV: y[b,m,h,d] = (sum_k x[b, m*16+k, h, d]*w[k] + sum_k pe[k,d]*w[k]) / 32
// x (4,16384,8,128) f32, w (32) f32, pe (32,128) f32, y (4,1023,8,128) f32.
//
// R7 = R6 (TMA bulk 3-stage ring, rolling A/B accumulators) with WCHUNK 4->2:
// 2048 short CTAs instead of 1024 long ones, shrinking the partial-wave DRAM
// idle tail (3.46 waves of 13us CTAs -> ~7 waves of 6.6us CTAs). Boundary
// group overlap rises to 1.5x at issue; L2 dedups it to 1.0x at DRAM (proven
// in R6 at 1.25x).

#define CB 4
#define CN 16384
#define CH 8
#define CD 128
#define CK 32
#define CM 1023
#define WCHUNK 2                    // windows per CTA
#define NCHUNKS 512                 // ceil(1023/2)
#define GTOK 8                      // tokens per group
#define GROUP_BYTES (GTOK * CH * CD * 4)   // 32768
#define NGROUPS (2 * WCHUNK + 2)    // 6
#define STAGES 3
#define LANES 256                   // float4 lanes per token row
#define SMEM_DATA_OFF 1024
#define SMEM_TOTAL (SMEM_DATA_OFF + STAGES * GROUP_BYTES)   // 99328
#define MAX_T 2047                  // last valid 8-token group index

__device__ __forceinline__ uint32_t smem_u32(const void* p) {
    uint32_t a;
    asm("{ .reg .u64 t; cvta.to.shared.u64 t, %1; cvt.u32.u64 %0, t; }"
        : "=r"(a) : "l"(p));
    return a;
}

__device__ __forceinline__ void mbar_init(uint32_t mb, uint32_t cnt) {
    asm volatile("mbarrier.init.shared.b64 [%0], %1;" :: "r"(mb), "r"(cnt) : "memory");
}
__device__ __forceinline__ void mbar_expect_tx(uint32_t mb, uint32_t bytes) {
    asm volatile("mbarrier.arrive.expect_tx.shared.b64 _, [%0], %1;"
                 :: "r"(mb), "r"(bytes) : "memory");
}
__device__ __forceinline__ void mbar_wait(uint32_t mb, uint32_t parity) {
    asm volatile(
        "{\n\t"
        ".reg .pred P;\n\t"
        "WL_%=:\n\t"
        "mbarrier.try_wait.parity.acquire.cta.shared::cta.b64 P, [%0], %1, 0x989680;\n\t"
        "@P bra.uni WD_%=;\n\t"
        "bra.uni WL_%=;\n\t"
        "WD_%=:\n\t"
        "}"
        :: "r"(mb), "r"(parity) : "memory");
}
__device__ __forceinline__ void bulk_ld(uint32_t dst, const void* src, uint32_t mb) {
    asm volatile("cp.async.bulk.shared::cta.global.mbarrier::complete_tx::bytes "
                 "[%0], [%1], %2, [%3];"
                 :: "r"(dst), "l"(src), "n"(GROUP_BYTES), "r"(mb) : "memory");
}

__global__ __launch_bounds__(256, 2)
void compresskv_kernel(const float* __restrict__ x,
                       const float* __restrict__ w,
                       const float4* __restrict__ pe,
                       float4*      __restrict__ y)
{
    extern __shared__ char smem[];
    const uint32_t sbase = smem_u32(smem);
    const int tid = threadIdx.x;
    const int m0  = blockIdx.x * WCHUNK;
    const int b   = blockIdx.y;
    const int t0  = 2 * m0;                  // first global 8-token group

    if (tid == 0) {
#pragma unroll
        for (int s = 0; s < STAGES; ++s) mbar_init(sbase + 8u * s, 1);
    }
    __syncthreads();

    const char* xb = (const char*)x + (size_t)b * CN * (CH * CD * 4);

    // prologue: fill the ring
    if (tid == 0) {
#pragma unroll
        for (int j = 0; j < STAGES; ++j) {
            if (t0 + j <= MAX_T) {
                mbar_expect_tx(sbase + 8u * j, GROUP_BYTES);
                bulk_ld(sbase + SMEM_DATA_OFF + (uint32_t)j * GROUP_BYTES,
                        xb + (size_t)(t0 + j) * GROUP_BYTES, sbase + 8u * j);
            }
        }
    }

    // weights + bias (registers; pe is 16 KB, L2 resident)
    float wk[CK];
#pragma unroll
    for (int k = 0; k < CK; ++k) wk[k] = __ldg(&w[k]);

    float4 bias; bias.x = bias.y = bias.z = bias.w = 0.f;
#pragma unroll
    for (int k = 0; k < CK; ++k) {
        float4 p = __ldg(&pe[k * (CD / 4) + (tid & 31)]);
        bias.x = fmaf(wk[k], p.x, bias.x);
        bias.y = fmaf(wk[k], p.y, bias.y);
        bias.z = fmaf(wk[k], p.z, bias.z);
        bias.w = fmaf(wk[k], p.w, bias.w);
    }

    float4* yb = y + (size_t)b * CM * LANES + tid;

    float aAx = 0.f, aAy = 0.f, aAz = 0.f, aAw = 0.f;   // older window
    float aBx = 0.f, aBy = 0.f, aBz = 0.f, aBw = 0.f;   // newer window

#pragma unroll
    for (int j = 0; j < NGROUPS; ++j) {
        if (t0 + j <= MAX_T) {                           // uniform per block
            const int st = j % STAGES;
            mbar_wait(sbase + 8u * st, (j / STAGES) & 1);

            const float4* sp =
                (const float4*)(smem + SMEM_DATA_OFF + (size_t)st * GROUP_BYTES) + tid;
            const int koffB = 8 * (j & 1);               // compile-time
            const int koffA = 16 + 8 * (j & 1);
#pragma unroll
            for (int r = 0; r < GTOK; ++r) {
                float4 v = sp[r * LANES];
                if (j >= 2) {                            // older window is ours
                    aAx = fmaf(wk[koffA + r], v.x, aAx);
                    aAy = fmaf(wk[koffA + r], v.y, aAy);
                    aAz = fmaf(wk[koffA + r], v.z, aAz);
                    aAw = fmaf(wk[koffA + r], v.w, aAw);
                }
                if (j <= 2 * WCHUNK - 1) {               // newer window is ours
                    aBx = fmaf(wk[koffB + r], v.x, aBx);
                    aBy = fmaf(wk[koffB + r], v.y, aBy);
                    aBz = fmaf(wk[koffB + r], v.z, aBz);
                    aBw = fmaf(wk[koffB + r], v.w, aBw);
                }
            }
            __syncthreads();                             // stage st free
            if (tid == 0 && j + STAGES < NGROUPS && t0 + j + STAGES <= MAX_T) {
                mbar_expect_tx(sbase + 8u * st, GROUP_BYTES);
                bulk_ld(sbase + SMEM_DATA_OFF + (uint32_t)st * GROUP_BYTES,
                        xb + (size_t)(t0 + j + STAGES) * GROUP_BYTES, sbase + 8u * st);
            }

            if (j & 1) {                                 // window transition
                if (j >= 3) {
                    const int wdx = m0 + (j - 3) / 2;    // complete window
                    if (wdx <= CM - 1) {
                        float4 o;
                        o.x = (aAx + bias.x) * 0.03125f;
                        o.y = (aAy + bias.y) * 0.03125f;
                        o.z = (aAz + bias.z) * 0.03125f;
                        o.w = (aAw + bias.w) * 0.03125f;
                        yb[(size_t)wdx * LANES] = o;
                    }
                }
                aAx = aBx; aAy = aBy; aAz = aBz; aAw = aBw;
                aBx = 0.f; aBy = 0.f; aBz = 0.f; aBw = 0.f;
            }
        }
    }
}

extern "C" void kernel_launch(void* const* d_in, const int* in_sizes, int n_in,
                              void* d_out, int out_size)
{
    const float*  x  = (const float*) d_in[0];
    const float*  w  = (const float*) d_in[1];
    const float4* pe = (const float4*)d_in[2];
    float4*       y  = (float4*)d_out;

    static bool attr_set = false;
    if (!attr_set) {
        cudaFuncSetAttribute(compresskv_kernel,
                             cudaFuncAttributeMaxDynamicSharedMemorySize, SMEM_TOTAL);
        attr_set = true;
    }

    dim3 grid(NCHUNKS, CB);                  // (512, 4) = 2048 CTAs
    dim3 block(256);
    compresskv_kernel<<<grid, block, SMEM_TOTAL>>>(x, w, pe, y);
}